// round 3
// baseline (speedup 1.0000x reference)
#include <cuda_runtime.h>

#define BB 64
#define SS 128
#define TT 128
#define EE 512
#define HH 1024
#define NCTA 148
#define NTHR 256

// ---------------- static scratch ----------------
__device__ float g_proj_key[BB * SS * HH];
__device__ float g_gi_emb[BB * TT * 3 * HH];    // emb@W_ih^T + b_ih
__device__ float g_pre_emb[BB * TT * HH];       // emb@preW_emb^T
__device__ float g_h[BB * HH];
__device__ float g_ctx[BB * 2 * HH];
__device__ float g_scores[BB * SS];
__device__ float g_qpart[4][BB * HH];
__device__ float g_ghpart[4][BB * 3 * HH];
__device__ float g_gipart[8][BB * 3 * HH];
__device__ float g_pcpart[8][BB * HH];
__device__ float g_phpart[4][BB * HH];
__device__ unsigned g_ctr;

// ---------------- FMA-only fast tanh ----------------
__device__ __forceinline__ float fast_tanh(float x) {
    float ax = fminf(fabsf(x), 9.0f);
    float t = ax * 2.8853900817779268f;
    float fi = rintf(t);
    float f = t - fi;
    float p = 1.3333558e-3f;
    p = fmaf(p, f, 9.6181291e-3f);
    p = fmaf(p, f, 5.5504109e-2f);
    p = fmaf(p, f, 2.4022651e-1f);
    p = fmaf(p, f, 6.9314718e-1f);
    p = fmaf(p, f, 1.0f);
    float e = __int_as_float((127 + (int)fi) << 23) * p;
    float d = e + 1.0f;
    float r = __int_as_float(0x7EF311C3 - __float_as_int(d));
    r = r * (2.0f - d * r);
    r = r * (2.0f - d * r);
    r = r * (2.0f - d * r);
    return copysignf(fmaf(-2.0f, r, 1.0f), x);
}
__device__ __forceinline__ float sigmoidf_(float x) { return 1.0f / (1.0f + __expf(-x)); }

// ---------------- grid-wide barrier (monotonic counter) ----------------
__device__ __forceinline__ void gsync(unsigned& epoch) {
    __syncthreads();
    if (threadIdx.x == 0) {
        __threadfence();                       // release
        epoch++;
        atomicAdd(&g_ctr, 1u);
        unsigned target = epoch * NCTA;
        while (atomicAdd(&g_ctr, 0u) < target) __nanosleep(128);
        __threadfence();                       // acquire: invalidate this SM's L1
    }
    __syncthreads();
}

// ---------------- 64x32 GEMM unit, K-chunk = 256 ----------------
__device__ __forceinline__ void gemm_unit(const float* __restrict__ Abase, int lda,
                                          const float* __restrict__ Wbase, int ldw,
                                          float* __restrict__ C, int ldc,
                                          float* As, float* Ws) {
    int tid = threadIdx.x;
    int nhat = tid & 15, mhat = tid >> 4;
    int lr = tid >> 3, lc = (tid & 7) << 2;
    float acc[4][2] = {};
    for (int k0 = 0; k0 < 256; k0 += 32) {
        float4 a0 = *(const float4*)(Abase + lr * lda + k0 + lc);
        float4 a1 = *(const float4*)(Abase + (lr + 32) * lda + k0 + lc);
        float4 w0 = *(const float4*)(Wbase + lr * ldw + k0 + lc);
        __syncthreads();
        As[(lc + 0) * 68 + lr] = a0.x; As[(lc + 1) * 68 + lr] = a0.y;
        As[(lc + 2) * 68 + lr] = a0.z; As[(lc + 3) * 68 + lr] = a0.w;
        As[(lc + 0) * 68 + lr + 32] = a1.x; As[(lc + 1) * 68 + lr + 32] = a1.y;
        As[(lc + 2) * 68 + lr + 32] = a1.z; As[(lc + 3) * 68 + lr + 32] = a1.w;
        Ws[(lc + 0) * 34 + lr] = w0.x; Ws[(lc + 1) * 34 + lr] = w0.y;
        Ws[(lc + 2) * 34 + lr] = w0.z; Ws[(lc + 3) * 34 + lr] = w0.w;
        __syncthreads();
        #pragma unroll
        for (int kk = 0; kk < 32; kk++) {
            float4 av = *(const float4*)&As[kk * 68 + (mhat << 2)];
            float2 wv = *(const float2*)&Ws[kk * 34 + (nhat << 1)];
            acc[0][0] = fmaf(av.x, wv.x, acc[0][0]);
            acc[0][1] = fmaf(av.x, wv.y, acc[0][1]);
            acc[1][0] = fmaf(av.y, wv.x, acc[1][0]);
            acc[1][1] = fmaf(av.y, wv.y, acc[1][1]);
            acc[2][0] = fmaf(av.z, wv.x, acc[2][0]);
            acc[2][1] = fmaf(av.z, wv.y, acc[2][1]);
            acc[3][0] = fmaf(av.w, wv.x, acc[3][0]);
            acc[3][1] = fmaf(av.w, wv.y, acc[3][1]);
        }
    }
    int mbase = mhat << 2, nbase = nhat << 1;
    #pragma unroll
    for (int i = 0; i < 4; i++)
        #pragma unroll
        for (int j = 0; j < 2; j++)
            C[(mbase + i) * ldc + nbase + j] = acc[i][j];
}

// ---------------- unit bodies ----------------
__device__ void scores_unit(int b, int sc, const float* __restrict__ ew, float* qs, float* ws) {
    int tid = threadIdx.x;
    __syncthreads();
    for (int i = tid; i < HH; i += NTHR) {
        float v = g_qpart[0][b * HH + i] + g_qpart[1][b * HH + i]
                + g_qpart[2][b * HH + i] + g_qpart[3][b * HH + i];
        qs[i] = v; ws[i] = ew[i];
    }
    __syncthreads();
    int warp = tid >> 5, lane = tid & 31;
    #pragma unroll
    for (int r = 0; r < 4; r++) {
        int s = sc * 32 + warp * 4 + r;
        const float* p = g_proj_key + (b * SS + s) * HH;
        float acc = 0.f;
        for (int h = lane * 4; h < HH; h += 128) {
            float4 pv = *(const float4*)(p + h);
            acc += fast_tanh(qs[h + 0] + pv.x) * ws[h + 0];
            acc += fast_tanh(qs[h + 1] + pv.y) * ws[h + 1];
            acc += fast_tanh(qs[h + 2] + pv.z) * ws[h + 2];
            acc += fast_tanh(qs[h + 3] + pv.w) * ws[h + 3];
        }
        #pragma unroll
        for (int o = 16; o; o >>= 1) acc += __shfl_xor_sync(0xffffffffu, acc, o);
        if (lane == 0) g_scores[b * SS + s] = acc;
    }
}

__device__ void ctx_unit(int b, int nc, const float* __restrict__ enc, float* sm) {
    float* ev = sm;            // [128]
    float* red = sm + SS;      // [8]
    int tid = threadIdx.x, warp = tid >> 5, lane = tid & 31;
    __syncthreads();
    float sv = (tid < SS) ? g_scores[b * SS + tid] : -3.0e38f;
    float m = sv;
    #pragma unroll
    for (int o = 16; o; o >>= 1) m = fmaxf(m, __shfl_xor_sync(0xffffffffu, m, o));
    if (lane == 0) red[warp] = m;
    __syncthreads();
    if (warp == 0) {
        float v = (lane < 8) ? red[lane] : -3.0e38f;
        #pragma unroll
        for (int o = 4; o; o >>= 1) v = fmaxf(v, __shfl_xor_sync(0xffffffffu, v, o));
        if (lane == 0) red[0] = v;
    }
    __syncthreads();
    float bmax = red[0];
    __syncthreads();
    float e = (tid < SS) ? __expf(sv - bmax) : 0.f;
    if (tid < SS) ev[tid] = e;
    float su = e;
    #pragma unroll
    for (int o = 16; o; o >>= 1) su += __shfl_xor_sync(0xffffffffu, su, o);
    if (lane == 0) red[warp] = su;
    __syncthreads();
    if (tid == 0) {
        float ts = 0.f;
        #pragma unroll
        for (int i = 0; i < 8; i++) ts += red[i];
        sm[136] = 1.0f / ts;
    }
    __syncthreads();
    float inv = sm[136];
    int n = nc * 256 + tid;
    const float* eb = enc + b * SS * 2 * HH + n;
    float acc = 0.f;
    #pragma unroll 8
    for (int s = 0; s < SS; s++) acc = fmaf(ev[s], eb[s * 2 * HH], acc);
    g_ctx[b * 2 * HH + n] = acc * inv;
}

// ---------------- persistent decoder loop ----------------
__global__ void __launch_bounds__(NTHR, 1) decoder_loop(
    const float* __restrict__ enc, const float* __restrict__ qW,
    const float* __restrict__ ew, const float* __restrict__ W_ih,
    const float* __restrict__ W_hh, const float* __restrict__ b_hh,
    const float* __restrict__ preW,
    float* __restrict__ out_states, float* __restrict__ out_hfinal,
    float* __restrict__ out_pre) {
    __shared__ float sm[32 * 68 + 32 * 34];
    float* As = sm;
    float* Ws = sm + 32 * 68;
    float* qs = sm;
    float* ws = sm + HH;
    unsigned epoch = 0;
    const int bid = blockIdx.x;
    const int tid = threadIdx.x;
    const int ldw_ih = EE + 2 * HH;
    const int ldw_pre = EE + 3 * HH;
    const float* preW_h = preW + EE;
    const float* preW_c = preW + EE + HH;

    for (int t = 0; t < TT; t++) {
        // ---- Pa: q(t) [128u] + preout-h(t-1) [128u] ----
        {
            int nu = (t > 0) ? 256 : 128;
            for (int u = bid; u < nu; u += NCTA) {
                if (u < 128) {
                    int kc = u >> 5, nt = u & 31;
                    gemm_unit(g_h + kc * 256, HH, qW + nt * 32 * HH + kc * 256, HH,
                              g_qpart[kc] + nt * 32, HH, As, Ws);
                } else {
                    int v = u - 128; int kc = v >> 5, nt = v & 31;
                    gemm_unit(g_h + kc * 256, HH, preW_h + nt * 32 * ldw_pre + kc * 256, ldw_pre,
                              g_phpart[kc] + nt * 32, HH, As, Ws);
                }
            }
        }
        gsync(epoch);
        // ---- Pb: scores(t) [256u] + preout-final(t-1) [64u] ----
        {
            int nu = (t > 0) ? 320 : 256;
            for (int u = bid; u < nu; u += NCTA) {
                if (u < 256) {
                    scores_unit(u >> 2, u & 3, ew, qs, ws);
                } else {
                    int v = u - 256;
                    for (int e = tid; e < 1024; e += NTHR) {
                        int i = v * 1024 + e;
                        int b = i >> 10, k = i & 1023;
                        float val = g_pre_emb[(b * TT + (t - 1)) * HH + k];
                        #pragma unroll
                        for (int p = 0; p < 8; p++) val += g_pcpart[p][i];
                        #pragma unroll
                        for (int p = 0; p < 4; p++) val += g_phpart[p][i];
                        out_pre[(b * TT + (t - 1)) * HH + k] = val;
                    }
                }
            }
        }
        gsync(epoch);
        // ---- Pc: ctx(t) [512u] + gh(t) [384u] ----
        for (int u = bid; u < 896; u += NCTA) {
            if (u < 512) {
                ctx_unit(u >> 3, u & 7, enc, sm);
            } else {
                int v = u - 512; int kc = v / 96, nt = v - kc * 96;
                gemm_unit(g_h + kc * 256, HH, W_hh + nt * 32 * HH + kc * 256, HH,
                          g_ghpart[kc] + nt * 32, 3 * HH, As, Ws);
            }
        }
        gsync(epoch);
        // ---- Pd: gi(t) [768u] + prectx(t) [256u] ----
        for (int u = bid; u < 1024; u += NCTA) {
            if (u < 768) {
                int kc = u / 96, nt = u - kc * 96;
                gemm_unit(g_ctx + kc * 256, 2 * HH,
                          W_ih + EE + nt * 32 * ldw_ih + kc * 256, ldw_ih,
                          g_gipart[kc] + nt * 32, 3 * HH, As, Ws);
            } else {
                int v = u - 768; int kc = v >> 5, nt = v & 31;
                gemm_unit(g_ctx + kc * 256, 2 * HH,
                          preW_c + nt * 32 * ldw_pre + kc * 256, ldw_pre,
                          g_pcpart[kc] + nt * 32, HH, As, Ws);
            }
        }
        gsync(epoch);
        // ---- Pe: GRU combine ----
        for (int idx = bid * NTHR + tid; idx < BB * HH; idx += NCTA * NTHR) {
            int b = idx >> 10, k = idx & 1023;
            int r0 = b * 3 * HH + k;
            float ir = g_gi_emb[(b * TT + t) * 3 * HH + k];
            float iz = g_gi_emb[(b * TT + t) * 3 * HH + HH + k];
            float in_ = g_gi_emb[(b * TT + t) * 3 * HH + 2 * HH + k];
            #pragma unroll
            for (int p = 0; p < 8; p++) {
                ir  += g_gipart[p][r0];
                iz  += g_gipart[p][r0 + HH];
                in_ += g_gipart[p][r0 + 2 * HH];
            }
            float hr = b_hh[k], hz = b_hh[HH + k], hn = b_hh[2 * HH + k];
            #pragma unroll
            for (int p = 0; p < 4; p++) {
                hr += g_ghpart[p][r0];
                hz += g_ghpart[p][r0 + HH];
                hn += g_ghpart[p][r0 + 2 * HH];
            }
            float hp = g_h[idx];
            float r = sigmoidf_(ir + hr);
            float z = sigmoidf_(iz + hz);
            float n = fast_tanh(fmaf(r, hn, in_));
            float hnew = fmaf(z, hp - n, n);
            g_h[idx] = hnew;
            out_states[(b * TT + t) * HH + k] = hnew;
            if (t == TT - 1) out_hfinal[idx] = hnew;
        }
        gsync(epoch);
    }
    // ---- tail: preout-h(127) + preout-final(127) ----
    for (int u = bid; u < 128; u += NCTA) {
        int kc = u >> 5, nt = u & 31;
        gemm_unit(g_h + kc * 256, HH, preW_h + nt * 32 * ldw_pre + kc * 256, ldw_pre,
                  g_phpart[kc] + nt * 32, HH, As, Ws);
    }
    gsync(epoch);
    for (int u = bid; u < 64; u += NCTA) {
        for (int e = tid; e < 1024; e += NTHR) {
            int i = u * 1024 + e;
            int b = i >> 10, k = i & 1023;
            float val = g_pre_emb[(b * TT + TT - 1) * HH + k];
            #pragma unroll
            for (int p = 0; p < 8; p++) val += g_pcpart[p][i];
            #pragma unroll
            for (int p = 0; p < 4; p++) val += g_phpart[p][i];
            out_pre[(b * TT + TT - 1) * HH + k] = val;
        }
    }
}

__global__ void zero_ctr() { g_ctr = 0u; }

// ---------------- precompute GEMM ----------------
struct GemmDesc {
    const float* A; const float* W; float* C;
    const float* bias;
    int lda, ldw, ldc;
    int K, n_tiles, cta_begin, act;
};
struct GemmArgs { GemmDesc d[4]; int n; };

__global__ void __launch_bounds__(256) gemm_multi(GemmArgs ga) {
    int bx = blockIdx.x;
    int di = 0;
    if (ga.n > 1 && bx >= ga.d[1].cta_begin) di = 1;
    if (ga.n > 2 && bx >= ga.d[2].cta_begin) di = 2;
    if (ga.n > 3 && bx >= ga.d[3].cta_begin) di = 3;
    GemmDesc g = ga.d[di];
    int local = bx - g.cta_begin;
    int mtile = local / g.n_tiles;
    int ntile = local - mtile * g.n_tiles;
    const float* Abase = g.A + mtile * 64 * g.lda;
    const float* Wbase = g.W + ntile * 32 * g.ldw;
    __shared__ float As[32][68];
    __shared__ float Ws[32][34];
    int tid = threadIdx.x;
    int nhat = tid & 15, mhat = tid >> 4;
    int lr = tid >> 3, lc = (tid & 7) << 2;
    float acc[4][2] = {};
    for (int k0 = 0; k0 < g.K; k0 += 32) {
        float4 a0 = *(const float4*)(Abase + lr * g.lda + k0 + lc);
        float4 a1 = *(const float4*)(Abase + (lr + 32) * g.lda + k0 + lc);
        float4 w0 = *(const float4*)(Wbase + lr * g.ldw + k0 + lc);
        As[lc + 0][lr] = a0.x; As[lc + 1][lr] = a0.y; As[lc + 2][lr] = a0.z; As[lc + 3][lr] = a0.w;
        As[lc + 0][lr + 32] = a1.x; As[lc + 1][lr + 32] = a1.y; As[lc + 2][lr + 32] = a1.z; As[lc + 3][lr + 32] = a1.w;
        Ws[lc + 0][lr] = w0.x; Ws[lc + 1][lr] = w0.y; Ws[lc + 2][lr] = w0.z; Ws[lc + 3][lr] = w0.w;
        __syncthreads();
        #pragma unroll
        for (int kk = 0; kk < 32; kk++) {
            float4 av = *(const float4*)&As[kk][mhat << 2];
            float2 wv = *(const float2*)&Ws[kk][nhat << 1];
            acc[0][0] = fmaf(av.x, wv.x, acc[0][0]);
            acc[0][1] = fmaf(av.x, wv.y, acc[0][1]);
            acc[1][0] = fmaf(av.y, wv.x, acc[1][0]);
            acc[1][1] = fmaf(av.y, wv.y, acc[1][1]);
            acc[2][0] = fmaf(av.z, wv.x, acc[2][0]);
            acc[2][1] = fmaf(av.z, wv.y, acc[2][1]);
            acc[3][0] = fmaf(av.w, wv.x, acc[3][0]);
            acc[3][1] = fmaf(av.w, wv.y, acc[3][1]);
        }
        __syncthreads();
    }
    int mbase = mtile * 64 + (mhat << 2);
    int nbase = ntile * 32 + (nhat << 1);
    #pragma unroll
    for (int i = 0; i < 4; i++)
        #pragma unroll
        for (int j = 0; j < 2; j++) {
            int m = mbase + i, n = nbase + j;
            float v = acc[i][j];
            if (g.bias) v += g.bias[n];
            if (g.act)  v = fast_tanh(v);
            g.C[m * g.ldc + n] = v;
        }
}

static GemmDesc mk(const float* A, int lda, const float* W, int ldw, float* C, int ldc,
                   int K, int n_tiles, int cta_begin,
                   const float* bias = nullptr, int act = 0) {
    GemmDesc d;
    d.A = A; d.W = W; d.C = C; d.bias = bias;
    d.lda = lda; d.ldw = ldw; d.ldc = ldc;
    d.K = K; d.n_tiles = n_tiles; d.cta_begin = cta_begin; d.act = act;
    return d;
}

extern "C" void kernel_launch(void* const* d_in, const int* in_sizes, int n_in,
                              void* d_out, int out_size) {
    const float* trg_embed  = (const float*)d_in[0];
    const float* enc_hidden = (const float*)d_in[1];
    const float* enc_final  = (const float*)d_in[2];
    const float* key_W    = (const float*)d_in[4];
    const float* query_W  = (const float*)d_in[5];
    const float* energy_w = (const float*)d_in[6];
    const float* W_ih     = (const float*)d_in[7];
    const float* W_hh     = (const float*)d_in[8];
    const float* b_ih     = (const float*)d_in[9];
    const float* b_hh     = (const float*)d_in[10];
    const float* bridge_W = (const float*)d_in[11];
    const float* bridge_b = (const float*)d_in[12];
    const float* preout_W = (const float*)d_in[13];

    float *p_pk, *p_giemb, *p_preemb, *p_h;
    cudaGetSymbolAddress((void**)&p_pk,     g_proj_key);
    cudaGetSymbolAddress((void**)&p_giemb,  g_gi_emb);
    cudaGetSymbolAddress((void**)&p_preemb, g_pre_emb);
    cudaGetSymbolAddress((void**)&p_h,      g_h);

    float* out_states = (float*)d_out;
    float* out_hfinal = out_states + BB * TT * HH;
    float* out_pre    = out_hfinal + BB * HH;

    // ---- precompute: proj_key, GI_emb(+b_ih), PRE_emb, h0 ----
    {
        GemmArgs pa; pa.n = 4;
        pa.d[0] = mk(enc_hidden, 2 * HH, key_W, 2 * HH, p_pk, HH, 2 * HH, 32, 0);
        pa.d[1] = mk(trg_embed, EE, W_ih, EE + 2 * HH, p_giemb, 3 * HH, EE, 96, 4096, b_ih);
        pa.d[2] = mk(trg_embed, EE, preout_W, 3 * HH + EE, p_preemb, HH, EE, 32, 16384);
        pa.d[3] = mk(enc_final, 2 * HH, bridge_W, 2 * HH, p_h, HH, 2 * HH, 32, 20480,
                     bridge_b, 1);
        gemm_multi<<<20512, 256>>>(pa);
    }
    zero_ctr<<<1, 1>>>();
    decoder_loop<<<NCTA, NTHR>>>(enc_hidden, query_W, energy_w, W_ih, W_hh, b_hh,
                                 preout_W, out_states, out_hfinal, out_pre);
}

// round 7
// speedup vs baseline: 1.6842x; 1.6842x over previous
#include <cuda_runtime.h>
#include <cuda_bf16.h>

#define BB 64
#define SS 128
#define TT 128
#define EE 512
#define HH 1024
#define NCTA 148
#define NTHR 256

typedef __nv_bfloat16 bf16;

// smem: words, stride 68 words (136 bf16) per row
#define SMW_A 68
#define SM_AHI 0
#define SM_ALO (64 * 68)
#define SM_WHI (2 * 64 * 68)
#define SM_WLO (2 * 64 * 68 + 128 * 68)
#define SM_WORDS (2 * 64 * 68 + 2 * 128 * 68)   // 26112 words = 104448 B

// ---------------- static scratch ----------------
__device__ float g_proj_key[BB * SS * HH];
__device__ float g_gi_emb[BB * TT * 3 * HH];      // emb@W_ih^T + b_ih
__device__ float g_pre_emb[BB * TT * HH];
__device__ float g_h[BB * HH];
__device__ float g_scores[BB * SS];
__device__ unsigned g_ctr;
// splits
__device__ bf16 g_ehi[BB * SS * 2 * HH], g_elo[BB * SS * 2 * HH];
__device__ bf16 g_thi[BB * TT * EE],     g_tlo[BB * TT * EE];
__device__ bf16 g_keyhi[HH * 2 * HH],    g_keylo[HH * 2 * HH];
__device__ bf16 g_qwhi[HH * HH],         g_qwlo[HH * HH];
__device__ bf16 g_whhhi[3 * HH * HH],    g_whhlo[3 * HH * HH];
__device__ bf16 g_wihhi[3 * HH * (EE + 2 * HH)], g_wihlo[3 * HH * (EE + 2 * HH)];
__device__ bf16 g_prehi[HH * (3 * HH + EE)],     g_prelo[HH * (3 * HH + EE)];
__device__ bf16 g_hhi[BB * HH],  g_hlo[BB * HH];
__device__ bf16 g_chi[BB * 2 * HH], g_clo[BB * 2 * HH];
// partials (fp32)
__device__ float g_qpart[8][BB * HH];
__device__ float g_ghpart[8][BB * 3 * HH];
__device__ float g_gipart[16][BB * 3 * HH];
__device__ float g_pcpart[16][BB * HH];
__device__ float g_phpart[8][BB * HH];

// ---------------- fast math ----------------
__device__ __forceinline__ float fast_tanh(float x) {
    float ax = fminf(fabsf(x), 9.0f);
    float t = ax * 2.8853900817779268f;
    float fi = rintf(t);
    float f = t - fi;
    float p = 1.3333558e-3f;
    p = fmaf(p, f, 9.6181291e-3f);
    p = fmaf(p, f, 5.5504109e-2f);
    p = fmaf(p, f, 2.4022651e-1f);
    p = fmaf(p, f, 6.9314718e-1f);
    p = fmaf(p, f, 1.0f);
    float e = __int_as_float((127 + (int)fi) << 23) * p;
    float d = e + 1.0f;
    float r = __int_as_float(0x7EF311C3 - __float_as_int(d));
    r = r * (2.0f - d * r);
    r = r * (2.0f - d * r);
    r = r * (2.0f - d * r);
    return copysignf(fmaf(-2.0f, r, 1.0f), x);
}
__device__ __forceinline__ float sigmoidf_(float x) { return 1.0f / (1.0f + __expf(-x)); }

// ---------------- grid barrier ----------------
__device__ __forceinline__ void gsync(unsigned& epoch) {
    __syncthreads();
    if (threadIdx.x == 0) {
        __threadfence();
        epoch++;
        atomicAdd(&g_ctr, 1u);
        unsigned target = epoch * NCTA;
        while (atomicAdd(&g_ctr, 0u) < target) __nanosleep(128);
        __threadfence();
    }
    __syncthreads();
}

// ---------------- mma ----------------
__device__ __forceinline__ void mma16816(float* d, unsigned a0, unsigned a1, unsigned a2,
                                         unsigned a3, unsigned b0, unsigned b1) {
    asm volatile(
        "mma.sync.aligned.m16n8k16.row.col.f32.bf16.bf16.f32 "
        "{%0,%1,%2,%3},{%4,%5,%6,%7},{%8,%9},{%0,%1,%2,%3};"
        : "+f"(d[0]), "+f"(d[1]), "+f"(d[2]), "+f"(d[3])
        : "r"(a0), "r"(a1), "r"(a2), "r"(a3), "r"(b0), "r"(b1));
}

// ---------------- 64x128 x (nkc*128) split-bf16 3-pass GEMM unit ----------------
// C[64, 128] = A[64, nkc*128] @ W[128, nkc*128]^T (+ bias), fp32 accumulate.
__device__ __noinline__ void mma_unit(const bf16* __restrict__ Ahi, const bf16* __restrict__ Alo,
                                      int lda,
                                      const bf16* __restrict__ Whi, const bf16* __restrict__ Wlo,
                                      int ldw,
                                      float* __restrict__ C, int ldc, int nkc,
                                      const float* __restrict__ bias, unsigned* sm) {
    const int tid = threadIdx.x;
    const int wid = tid >> 5, lane = tid & 31;
    const int wm = wid & 1, wn = wid >> 1;          // 2 m-warps x 4 n-warps
    const int g = lane >> 2, tg = lane & 3;
    unsigned* sAhi = sm + SM_AHI;
    unsigned* sAlo = sm + SM_ALO;
    unsigned* sWhi = sm + SM_WHI;
    unsigned* sWlo = sm + SM_WLO;
    float acc[2][4][4];
    #pragma unroll
    for (int a = 0; a < 2; a++)
        #pragma unroll
        for (int b = 0; b < 4; b++)
            #pragma unroll
            for (int c = 0; c < 4; c++) acc[a][b][c] = 0.f;

    for (int kc = 0; kc < nkc; kc++) {
        int k0 = kc * 128;
        __syncthreads();
        for (int i = tid; i < 1024; i += NTHR) {      // A: 64 rows x 16 uint4
            int row = i >> 4, seg = i & 15;
            *(uint4*)(sAhi + row * SMW_A + seg * 4) =
                *(const uint4*)(Ahi + row * lda + k0 + seg * 8);
            *(uint4*)(sAlo + row * SMW_A + seg * 4) =
                *(const uint4*)(Alo + row * lda + k0 + seg * 8);
        }
        for (int i = tid; i < 2048; i += NTHR) {      // W: 128 rows x 16 uint4
            int row = i >> 4, seg = i & 15;
            *(uint4*)(sWhi + row * SMW_A + seg * 4) =
                *(const uint4*)(Whi + row * ldw + k0 + seg * 8);
            *(uint4*)(sWlo + row * SMW_A + seg * 4) =
                *(const uint4*)(Wlo + row * ldw + k0 + seg * 8);
        }
        __syncthreads();
        #pragma unroll
        for (int ks = 0; ks < 8; ks++) {
            unsigned ah[2][4], al[2][4];
            #pragma unroll
            for (int mt = 0; mt < 2; mt++) {
                int base = (wm * 32 + mt * 16 + g) * SMW_A + ks * 8 + tg;
                ah[mt][0] = sAhi[base];           ah[mt][1] = sAhi[base + 8 * SMW_A];
                ah[mt][2] = sAhi[base + 4];       ah[mt][3] = sAhi[base + 8 * SMW_A + 4];
                al[mt][0] = sAlo[base];           al[mt][1] = sAlo[base + 8 * SMW_A];
                al[mt][2] = sAlo[base + 4];       al[mt][3] = sAlo[base + 8 * SMW_A + 4];
            }
            #pragma unroll
            for (int nt = 0; nt < 4; nt++) {
                int bb = (wn * 32 + nt * 8 + g) * SMW_A + ks * 8 + tg;
                unsigned bh0 = sWhi[bb], bh1 = sWhi[bb + 4];
                unsigned bl0 = sWlo[bb], bl1 = sWlo[bb + 4];
                #pragma unroll
                for (int mt = 0; mt < 2; mt++) {
                    mma16816(acc[mt][nt], ah[mt][0], ah[mt][1], ah[mt][2], ah[mt][3], bh0, bh1);
                    mma16816(acc[mt][nt], ah[mt][0], ah[mt][1], ah[mt][2], ah[mt][3], bl0, bl1);
                    mma16816(acc[mt][nt], al[mt][0], al[mt][1], al[mt][2], al[mt][3], bh0, bh1);
                }
            }
        }
    }
    #pragma unroll
    for (int mt = 0; mt < 2; mt++) {
        int r = wm * 32 + mt * 16 + g;
        #pragma unroll
        for (int nt = 0; nt < 4; nt++) {
            int cb = wn * 32 + nt * 8 + 2 * tg;
            float b0 = 0.f, b1 = 0.f;
            if (bias) { b0 = bias[cb]; b1 = bias[cb + 1]; }
            float2 v0 = {acc[mt][nt][0] + b0, acc[mt][nt][1] + b1};
            float2 v1 = {acc[mt][nt][2] + b0, acc[mt][nt][3] + b1};
            *(float2*)(C + r * ldc + cb) = v0;
            *(float2*)(C + (r + 8) * ldc + cb) = v1;
        }
    }
}

// ---------------- attention units ----------------
__device__ __noinline__ void scores_unit(int b, int sc, const float* __restrict__ ew, float* sm) {
    float* qs = sm;
    float* ws = sm + HH;
    int tid = threadIdx.x;
    __syncthreads();
    for (int i = tid; i < HH; i += NTHR) {
        float v = 0.f;
        #pragma unroll
        for (int p = 0; p < 8; p++) v += g_qpart[p][b * HH + i];
        qs[i] = v; ws[i] = ew[i];
    }
    __syncthreads();
    int warp = tid >> 5, lane = tid & 31;
    #pragma unroll
    for (int r = 0; r < 4; r++) {
        int s = sc * 32 + warp * 4 + r;
        const float* p = g_proj_key + (b * SS + s) * HH;
        float acc = 0.f;
        for (int h = lane * 4; h < HH; h += 128) {
            float4 pv = *(const float4*)(p + h);
            acc += fast_tanh(qs[h + 0] + pv.x) * ws[h + 0];
            acc += fast_tanh(qs[h + 1] + pv.y) * ws[h + 1];
            acc += fast_tanh(qs[h + 2] + pv.z) * ws[h + 2];
            acc += fast_tanh(qs[h + 3] + pv.w) * ws[h + 3];
        }
        #pragma unroll
        for (int o = 16; o; o >>= 1) acc += __shfl_xor_sync(0xffffffffu, acc, o);
        if (lane == 0) g_scores[b * SS + s] = acc;
    }
}

__device__ __noinline__ void ctx_unit(int b, int nc, const float* __restrict__ enc, float* sm) {
    float* ev = sm;
    float* red = sm + SS;
    int tid = threadIdx.x, warp = tid >> 5, lane = tid & 31;
    __syncthreads();
    float sv = (tid < SS) ? g_scores[b * SS + tid] : -3.0e38f;
    float m = sv;
    #pragma unroll
    for (int o = 16; o; o >>= 1) m = fmaxf(m, __shfl_xor_sync(0xffffffffu, m, o));
    if (lane == 0) red[warp] = m;
    __syncthreads();
    if (warp == 0) {
        float v = (lane < 8) ? red[lane] : -3.0e38f;
        #pragma unroll
        for (int o = 4; o; o >>= 1) v = fmaxf(v, __shfl_xor_sync(0xffffffffu, v, o));
        if (lane == 0) red[0] = v;
    }
    __syncthreads();
    float bmax = red[0];
    __syncthreads();
    float e = (tid < SS) ? __expf(sv - bmax) : 0.f;
    if (tid < SS) ev[tid] = e;
    float su = e;
    #pragma unroll
    for (int o = 16; o; o >>= 1) su += __shfl_xor_sync(0xffffffffu, su, o);
    if (lane == 0) red[warp] = su;
    __syncthreads();
    if (tid == 0) {
        float ts = 0.f;
        #pragma unroll
        for (int i = 0; i < 8; i++) ts += red[i];
        sm[136] = 1.0f / ts;
    }
    __syncthreads();
    float inv = sm[136];
    int n = nc * 256 + tid;
    const float* eb = enc + b * SS * 2 * HH + n;
    float acc = 0.f;
    #pragma unroll 8
    for (int s = 0; s < SS; s++) acc = fmaf(ev[s], eb[s * 2 * HH], acc);
    acc *= inv;
    int idx = b * 2 * HH + n;
    bf16 hi = __float2bfloat16(acc);
    g_chi[idx] = hi;
    g_clo[idx] = __float2bfloat16(acc - __bfloat162float(hi));
}

// ---------------- persistent decoder loop ----------------
__global__ void __launch_bounds__(NTHR, 1) decoder_loop(
    const float* __restrict__ enc, const float* __restrict__ ew,
    const float* __restrict__ b_hh,
    float* __restrict__ out_states, float* __restrict__ out_hfinal,
    float* __restrict__ out_pre) {
    extern __shared__ unsigned smext[];
    float* smf = (float*)smext;
    unsigned epoch = 0;
    const int bid = blockIdx.x;
    const int tid = threadIdx.x;
    const int ldw_ih = EE + 2 * HH;       // 2560
    const int ldw_pre = EE + 3 * HH;      // 3584

    for (int t = 0; t < TT; t++) {
        // ---- Pa: q [64u] + preout-h(prev state) [64u] ----
        for (int u = bid; u < 128; u += NCTA) {
            if (u < 64) {
                int nt = u & 7, kc = u >> 3;
                mma_unit(g_hhi + kc * 128, g_hlo + kc * 128, HH,
                         g_qwhi + nt * 128 * HH + kc * 128, g_qwlo + nt * 128 * HH + kc * 128, HH,
                         g_qpart[kc] + nt * 128, HH, 1, nullptr, smext);
            } else {
                int v = u - 64; int nt = v & 7, kc = v >> 3;
                mma_unit(g_hhi + kc * 128, g_hlo + kc * 128, HH,
                         g_prehi + nt * 128 * ldw_pre + EE + kc * 128,
                         g_prelo + nt * 128 * ldw_pre + EE + kc * 128, ldw_pre,
                         g_phpart[kc] + nt * 128, HH, 1, nullptr, smext);
            }
        }
        gsync(epoch);
        // ---- Pb: scores [256u] + preout-final(t-1) [64u] ----
        {
            int nu = (t > 0) ? 320 : 256;
            for (int u = bid; u < nu; u += NCTA) {
                if (u < 256) {
                    scores_unit(u >> 2, u & 3, ew, smf);
                } else {
                    int v = u - 256;
                    for (int e = tid; e < 1024; e += NTHR) {
                        int i = v * 1024 + e;
                        int b = i >> 10, k = i & 1023;
                        float val = g_pre_emb[(b * TT + (t - 1)) * HH + k];
                        #pragma unroll
                        for (int p = 0; p < 16; p++) val += g_pcpart[p][i];
                        #pragma unroll
                        for (int p = 0; p < 8; p++) val += g_phpart[p][i];
                        out_pre[(b * TT + (t - 1)) * HH + k] = val;
                    }
                }
            }
        }
        gsync(epoch);
        // ---- Pc: ctx [512u] + gh [192u] ----
        for (int u = bid; u < 704; u += NCTA) {
            if (u < 512) {
                ctx_unit(u >> 3, u & 7, enc, smf);
            } else {
                int v = u - 512; int nt = v % 24, kc = v / 24;
                mma_unit(g_hhi + kc * 128, g_hlo + kc * 128, HH,
                         g_whhhi + nt * 128 * HH + kc * 128, g_whhlo + nt * 128 * HH + kc * 128, HH,
                         g_ghpart[kc] + nt * 128, 3 * HH, 1, nullptr, smext);
            }
        }
        gsync(epoch);
        // ---- Pd: gi [384u] + prectx [128u] ----
        for (int u = bid; u < 512; u += NCTA) {
            if (u < 384) {
                int nt = u % 24, kc = u / 24;
                mma_unit(g_chi + kc * 128, g_clo + kc * 128, 2 * HH,
                         g_wihhi + nt * 128 * ldw_ih + EE + kc * 128,
                         g_wihlo + nt * 128 * ldw_ih + EE + kc * 128, ldw_ih,
                         g_gipart[kc] + nt * 128, 3 * HH, 1, nullptr, smext);
            } else {
                int v = u - 384; int nt = v & 7, kc = v >> 3;
                mma_unit(g_chi + kc * 128, g_clo + kc * 128, 2 * HH,
                         g_prehi + nt * 128 * ldw_pre + (EE + HH) + kc * 128,
                         g_prelo + nt * 128 * ldw_pre + (EE + HH) + kc * 128, ldw_pre,
                         g_pcpart[kc] + nt * 128, HH, 1, nullptr, smext);
            }
        }
        gsync(epoch);
        // ---- Pe: GRU combine + h split ----
        for (int idx = bid * NTHR + tid; idx < BB * HH; idx += NCTA * NTHR) {
            int b = idx >> 10, k = idx & 1023;
            int r0 = b * 3 * HH + k;
            float ir = g_gi_emb[(b * TT + t) * 3 * HH + k];
            float iz = g_gi_emb[(b * TT + t) * 3 * HH + HH + k];
            float in_ = g_gi_emb[(b * TT + t) * 3 * HH + 2 * HH + k];
            #pragma unroll
            for (int p = 0; p < 16; p++) {
                ir  += g_gipart[p][r0];
                iz  += g_gipart[p][r0 + HH];
                in_ += g_gipart[p][r0 + 2 * HH];
            }
            float hr = b_hh[k], hz = b_hh[HH + k], hn = b_hh[2 * HH + k];
            #pragma unroll
            for (int p = 0; p < 8; p++) {
                hr += g_ghpart[p][r0];
                hz += g_ghpart[p][r0 + HH];
                hn += g_ghpart[p][r0 + 2 * HH];
            }
            float hp = g_h[idx];
            float r = sigmoidf_(ir + hr);
            float z = sigmoidf_(iz + hz);
            float n = fast_tanh(fmaf(r, hn, in_));
            float hnew = fmaf(z, hp - n, n);
            g_h[idx] = hnew;
            bf16 hi = __float2bfloat16(hnew);
            g_hhi[idx] = hi;
            g_hlo[idx] = __float2bfloat16(hnew - __bfloat162float(hi));
            out_states[(b * TT + t) * HH + k] = hnew;
            if (t == TT - 1) out_hfinal[idx] = hnew;
        }
        gsync(epoch);
    }
    // ---- tail: preout-h(127) + final sum ----
    for (int u = bid; u < 64; u += NCTA) {
        int nt = u & 7, kc = u >> 3;
        mma_unit(g_hhi + kc * 128, g_hlo + kc * 128, HH,
                 g_prehi + nt * 128 * ldw_pre + EE + kc * 128,
                 g_prelo + nt * 128 * ldw_pre + EE + kc * 128, ldw_pre,
                 g_phpart[kc] + nt * 128, HH, 1, nullptr, smext);
    }
    gsync(epoch);
    for (int u = bid; u < 64; u += NCTA) {
        for (int e = tid; e < 1024; e += NTHR) {
            int i = u * 1024 + e;
            int b = i >> 10, k = i & 1023;
            float val = g_pre_emb[(b * TT + TT - 1) * HH + k];
            #pragma unroll
            for (int p = 0; p < 16; p++) val += g_pcpart[p][i];
            #pragma unroll
            for (int p = 0; p < 8; p++) val += g_phpart[p][i];
            out_pre[(b * TT + TT - 1) * HH + k] = val;
        }
    }
}

// ---------------- precompute mma kernel ----------------
__global__ void __launch_bounds__(NTHR) mma_pre(const float* __restrict__ b_ih,
                                                float* __restrict__ dummy) {
    extern __shared__ unsigned smext[];
    int u = blockIdx.x;
    if (u < 1024) {                      // proj_key: 128m x 8n, K=2048
        int mt = u >> 3, nt = u & 7;
        mma_unit(g_ehi + mt * 64 * (2 * HH), g_elo + mt * 64 * (2 * HH), 2 * HH,
                 g_keyhi + nt * 128 * (2 * HH), g_keylo + nt * 128 * (2 * HH), 2 * HH,
                 g_proj_key + mt * 64 * HH + nt * 128, HH, 16, nullptr, smext);
    } else if (u < 1024 + 3072) {        // gi_emb: 128m x 24n, K=512, + b_ih
        int v = u - 1024; int mt = v / 24, nt = v % 24;
        mma_unit(g_thi + mt * 64 * EE, g_tlo + mt * 64 * EE, EE,
                 g_wihhi + nt * 128 * (EE + 2 * HH), g_wihlo + nt * 128 * (EE + 2 * HH),
                 EE + 2 * HH,
                 g_gi_emb + mt * 64 * 3 * HH + nt * 128, 3 * HH, 4, b_ih + nt * 128, smext);
    } else {                             // pre_emb: 128m x 8n, K=512
        int v = u - 4096; int mt = v >> 3, nt = v & 7;
        mma_unit(g_thi + mt * 64 * EE, g_tlo + mt * 64 * EE, EE,
                 g_prehi + nt * 128 * (EE + 3 * HH), g_prelo + nt * 128 * (EE + 3 * HH),
                 EE + 3 * HH,
                 g_pre_emb + mt * 64 * HH + nt * 128, HH, 4, nullptr, smext);
    }
}

// ---------------- split kernel: fp32 -> bf16 hi + lo ----------------
__global__ void split_kernel(const float* __restrict__ src, bf16* __restrict__ hi,
                             bf16* __restrict__ lo, int n) {
    for (int i = (blockIdx.x * 256 + threadIdx.x) * 4; i < n; i += gridDim.x * 256 * 4) {
        float4 v = *(const float4*)(src + i);
        bf16 h0 = __float2bfloat16(v.x), h1 = __float2bfloat16(v.y);
        bf16 h2 = __float2bfloat16(v.z), h3 = __float2bfloat16(v.w);
        __nv_bfloat162* hp = (__nv_bfloat162*)(hi + i);
        hp[0] = __nv_bfloat162(h0, h1); hp[1] = __nv_bfloat162(h2, h3);
        __nv_bfloat162* lp = (__nv_bfloat162*)(lo + i);
        lp[0] = __nv_bfloat162(__float2bfloat16(v.x - __bfloat162float(h0)),
                               __float2bfloat16(v.y - __bfloat162float(h1)));
        lp[1] = __nv_bfloat162(__float2bfloat16(v.z - __bfloat162float(h2)),
                               __float2bfloat16(v.w - __bfloat162float(h3)));
    }
}

// ---------------- h0 SIMT GEMM: h0 = tanh(enc_final @ bridgeW^T + b) ----------------
__global__ void __launch_bounds__(256) gemm_h0(const float* __restrict__ A,
                                               const float* __restrict__ W,
                                               const float* __restrict__ bias,
                                               float* __restrict__ C) {
    int ntile = blockIdx.x;       // 32 tiles of 32 cols
    const float* Wbase = W + ntile * 32 * (2 * HH);
    __shared__ float As[32][68];
    __shared__ float Ws[32][34];
    int tid = threadIdx.x;
    int nhat = tid & 15, mhat = tid >> 4;
    int lr = tid >> 3, lc = (tid & 7) << 2;
    float acc[4][2] = {};
    for (int k0 = 0; k0 < 2 * HH; k0 += 32) {
        float4 a0 = *(const float4*)(A + lr * (2 * HH) + k0 + lc);
        float4 a1 = *(const float4*)(A + (lr + 32) * (2 * HH) + k0 + lc);
        float4 w0 = *(const float4*)(Wbase + lr * (2 * HH) + k0 + lc);
        __syncthreads();
        As[lc + 0][lr] = a0.x; As[lc + 1][lr] = a0.y; As[lc + 2][lr] = a0.z; As[lc + 3][lr] = a0.w;
        As[lc + 0][lr + 32] = a1.x; As[lc + 1][lr + 32] = a1.y;
        As[lc + 2][lr + 32] = a1.z; As[lc + 3][lr + 32] = a1.w;
        Ws[lc + 0][lr] = w0.x; Ws[lc + 1][lr] = w0.y; Ws[lc + 2][lr] = w0.z; Ws[lc + 3][lr] = w0.w;
        __syncthreads();
        #pragma unroll
        for (int kk = 0; kk < 32; kk++) {
            float4 av = *(const float4*)&As[kk][mhat << 2];
            float2 wv = *(const float2*)&Ws[kk][nhat << 1];
            acc[0][0] = fmaf(av.x, wv.x, acc[0][0]); acc[0][1] = fmaf(av.x, wv.y, acc[0][1]);
            acc[1][0] = fmaf(av.y, wv.x, acc[1][0]); acc[1][1] = fmaf(av.y, wv.y, acc[1][1]);
            acc[2][0] = fmaf(av.z, wv.x, acc[2][0]); acc[2][1] = fmaf(av.z, wv.y, acc[2][1]);
            acc[3][0] = fmaf(av.w, wv.x, acc[3][0]); acc[3][1] = fmaf(av.w, wv.y, acc[3][1]);
        }
    }
    int nbase = ntile * 32 + (nhat << 1);
    #pragma unroll
    for (int i = 0; i < 4; i++)
        #pragma unroll
        for (int j = 0; j < 2; j++) {
            int m = (mhat << 2) + i, n = nbase + j;
            C[m * HH + n] = fast_tanh(acc[i][j] + bias[n]);
        }
}

__global__ void zero_ctr() { g_ctr = 0u; }

// ---------------- host ----------------
extern "C" void kernel_launch(void* const* d_in, const int* in_sizes, int n_in,
                              void* d_out, int out_size) {
    const float* trg_embed  = (const float*)d_in[0];
    const float* enc_hidden = (const float*)d_in[1];
    const float* enc_final  = (const float*)d_in[2];
    const float* key_W    = (const float*)d_in[4];
    const float* query_W  = (const float*)d_in[5];
    const float* energy_w = (const float*)d_in[6];
    const float* W_ih     = (const float*)d_in[7];
    const float* W_hh     = (const float*)d_in[8];
    const float* b_ih     = (const float*)d_in[9];
    const float* b_hh     = (const float*)d_in[10];
    const float* bridge_W = (const float*)d_in[11];
    const float* bridge_b = (const float*)d_in[12];
    const float* preout_W = (const float*)d_in[13];

    // No static guards (harness rule): set attributes unconditionally.
    // cudaFuncSetAttribute is not a stream op, so it is graph-capture-safe.
    cudaFuncSetAttribute(decoder_loop, cudaFuncAttributeMaxDynamicSharedMemorySize,
                         SM_WORDS * 4);
    cudaFuncSetAttribute(mma_pre, cudaFuncAttributeMaxDynamicSharedMemorySize,
                         SM_WORDS * 4);

    bf16 *ehi, *elo, *thi, *tlo, *khi, *klo, *qhi, *qlo, *whi, *wlo, *ihi, *ilo, *phi, *plo,
         *hhi, *hlo;
    float* p_h;
    cudaGetSymbolAddress((void**)&ehi, g_ehi);  cudaGetSymbolAddress((void**)&elo, g_elo);
    cudaGetSymbolAddress((void**)&thi, g_thi);  cudaGetSymbolAddress((void**)&tlo, g_tlo);
    cudaGetSymbolAddress((void**)&khi, g_keyhi); cudaGetSymbolAddress((void**)&klo, g_keylo);
    cudaGetSymbolAddress((void**)&qhi, g_qwhi); cudaGetSymbolAddress((void**)&qlo, g_qwlo);
    cudaGetSymbolAddress((void**)&whi, g_whhhi); cudaGetSymbolAddress((void**)&wlo, g_whhlo);
    cudaGetSymbolAddress((void**)&ihi, g_wihhi); cudaGetSymbolAddress((void**)&ilo, g_wihlo);
    cudaGetSymbolAddress((void**)&phi, g_prehi); cudaGetSymbolAddress((void**)&plo, g_prelo);
    cudaGetSymbolAddress((void**)&hhi, g_hhi);  cudaGetSymbolAddress((void**)&hlo, g_hlo);
    cudaGetSymbolAddress((void**)&p_h, g_h);

    float* out_states = (float*)d_out;
    float* out_hfinal = out_states + BB * TT * HH;
    float* out_pre    = out_hfinal + BB * HH;

    // 1. split inputs + weights
    split_kernel<<<1024, 256>>>(enc_hidden, ehi, elo, BB * SS * 2 * HH);
    split_kernel<<<1024, 256>>>(trg_embed, thi, tlo, BB * TT * EE);
    split_kernel<<<512, 256>>>(key_W, khi, klo, HH * 2 * HH);
    split_kernel<<<512, 256>>>(query_W, qhi, qlo, HH * HH);
    split_kernel<<<512, 256>>>(W_hh, whi, wlo, 3 * HH * HH);
    split_kernel<<<1024, 256>>>(W_ih, ihi, ilo, 3 * HH * (EE + 2 * HH));
    split_kernel<<<512, 256>>>(preout_W, phi, plo, HH * (3 * HH + EE));
    // 2. h0 = tanh(bridge(enc_final)) + split
    gemm_h0<<<32, 256>>>(enc_final, bridge_W, bridge_b, p_h);
    split_kernel<<<64, 256>>>(p_h, hhi, hlo, BB * HH);
    // 3. precompute GEMMs (tensor cores)
    mma_pre<<<5120, 256, SM_WORDS * 4>>>(b_ih, nullptr);
    // 4. persistent decode loop
    zero_ctr<<<1, 1>>>();
    decoder_loop<<<NCTA, NTHR, SM_WORDS * 4>>>(enc_hidden, energy_w, b_hh,
                                               out_states, out_hfinal, out_pre);
}

// round 15
// speedup vs baseline: 2.3568x; 1.3993x over previous
#include <cuda_runtime.h>
#include <cuda_bf16.h>

#define BB 64
#define SS 128
#define TT 128
#define EE 512
#define HH 1024
#define NTHR 256

typedef __nv_bfloat16 bf16;

// smem: words, stride 68 words (136 bf16) per row
#define SMW_A 68
#define SM_AHI 0
#define SM_ALO (64 * 68)
#define SM_WHI (2 * 64 * 68)
#define SM_WLO (2 * 64 * 68 + 128 * 68)
#define SM_WORDS (2 * 64 * 68 + 2 * 128 * 68)   // 26112 words = 104448 B

// ---------------- static scratch ----------------
__device__ float g_proj_key[BB * SS * HH];
__device__ float g_gi_emb[BB * TT * 3 * HH];      // emb@W_ih^T + b_ih
__device__ float g_pre_emb[BB * TT * HH];
__device__ float g_h[BB * HH];
__device__ float g_scores[BB * SS];
__device__ unsigned g_ctr;
// splits
__device__ bf16 g_ehi[BB * SS * 2 * HH], g_elo[BB * SS * 2 * HH];
__device__ bf16 g_thi[BB * TT * EE],     g_tlo[BB * TT * EE];
__device__ bf16 g_keyhi[HH * 2 * HH],    g_keylo[HH * 2 * HH];
__device__ bf16 g_qwhi[HH * HH],         g_qwlo[HH * HH];
__device__ bf16 g_whhhi[3 * HH * HH],    g_whhlo[3 * HH * HH];
__device__ bf16 g_wihhi[3 * HH * (EE + 2 * HH)], g_wihlo[3 * HH * (EE + 2 * HH)];
__device__ bf16 g_prehi[HH * (3 * HH + EE)],     g_prelo[HH * (3 * HH + EE)];
__device__ bf16 g_hhi[BB * HH],  g_hlo[BB * HH];
__device__ bf16 g_chi[BB * 2 * HH], g_clo[BB * 2 * HH];
// partials (fp32)
__device__ float g_qpart[8][BB * HH];
__device__ float g_ghpart[8][BB * 3 * HH];
__device__ float g_gipart[16][BB * 3 * HH];
__device__ float g_pcpart[16][BB * HH];
__device__ float g_phpart[8][BB * HH];

// ---------------- fast math ----------------
__device__ __forceinline__ float fast_tanh(float x) {
    float ax = fminf(fabsf(x), 9.0f);
    float t = ax * 2.8853900817779268f;
    float fi = rintf(t);
    float f = t - fi;
    float p = 1.3333558e-3f;
    p = fmaf(p, f, 9.6181291e-3f);
    p = fmaf(p, f, 5.5504109e-2f);
    p = fmaf(p, f, 2.4022651e-1f);
    p = fmaf(p, f, 6.9314718e-1f);
    p = fmaf(p, f, 1.0f);
    float e = __int_as_float((127 + (int)fi) << 23) * p;
    float d = e + 1.0f;
    float r = __int_as_float(0x7EF311C3 - __float_as_int(d));
    r = r * (2.0f - d * r);
    r = r * (2.0f - d * r);
    r = r * (2.0f - d * r);
    return copysignf(fmaf(-2.0f, r, 1.0f), x);
}
__device__ __forceinline__ float sigmoidf_(float x) { return 1.0f / (1.0f + __expf(-x)); }

// ---------------- grid barrier (runtime CTA count) ----------------
__device__ __forceinline__ void gsync(unsigned& epoch, int ncta) {
    __syncthreads();
    if (threadIdx.x == 0) {
        __threadfence();
        epoch++;
        atomicAdd(&g_ctr, 1u);
        unsigned target = epoch * (unsigned)ncta;
        while (atomicAdd(&g_ctr, 0u) < target) __nanosleep(128);
        __threadfence();
    }
    __syncthreads();
}

// ---------------- mma ----------------
__device__ __forceinline__ void mma16816(float* d, unsigned a0, unsigned a1, unsigned a2,
                                         unsigned a3, unsigned b0, unsigned b1) {
    asm volatile(
        "mma.sync.aligned.m16n8k16.row.col.f32.bf16.bf16.f32 "
        "{%0,%1,%2,%3},{%4,%5,%6,%7},{%8,%9},{%0,%1,%2,%3};"
        : "+f"(d[0]), "+f"(d[1]), "+f"(d[2]), "+f"(d[3])
        : "r"(a0), "r"(a1), "r"(a2), "r"(a3), "r"(b0), "r"(b1));
}

// ---------------- 64x128 x (nkc*128) split-bf16 3-pass GEMM unit ----------------
__device__ __noinline__ void mma_unit(const bf16* __restrict__ Ahi, const bf16* __restrict__ Alo,
                                      int lda,
                                      const bf16* __restrict__ Whi, const bf16* __restrict__ Wlo,
                                      int ldw,
                                      float* __restrict__ C, int ldc, int nkc,
                                      const float* __restrict__ bias, unsigned* sm) {
    const int tid = threadIdx.x;
    const int wid = tid >> 5, lane = tid & 31;
    const int wm = wid & 1, wn = wid >> 1;
    const int g = lane >> 2, tg = lane & 3;
    unsigned* sAhi = sm + SM_AHI;
    unsigned* sAlo = sm + SM_ALO;
    unsigned* sWhi = sm + SM_WHI;
    unsigned* sWlo = sm + SM_WLO;
    float acc[2][4][4];
    #pragma unroll
    for (int a = 0; a < 2; a++)
        #pragma unroll
        for (int b = 0; b < 4; b++)
            #pragma unroll
            for (int c = 0; c < 4; c++) acc[a][b][c] = 0.f;

    for (int kc = 0; kc < nkc; kc++) {
        int k0 = kc * 128;
        __syncthreads();
        for (int i = tid; i < 1024; i += NTHR) {
            int row = i >> 4, seg = i & 15;
            *(uint4*)(sAhi + row * SMW_A + seg * 4) =
                *(const uint4*)(Ahi + row * lda + k0 + seg * 8);
            *(uint4*)(sAlo + row * SMW_A + seg * 4) =
                *(const uint4*)(Alo + row * lda + k0 + seg * 8);
        }
        for (int i = tid; i < 2048; i += NTHR) {
            int row = i >> 4, seg = i & 15;
            *(uint4*)(sWhi + row * SMW_A + seg * 4) =
                *(const uint4*)(Whi + row * ldw + k0 + seg * 8);
            *(uint4*)(sWlo + row * SMW_A + seg * 4) =
                *(const uint4*)(Wlo + row * ldw + k0 + seg * 8);
        }
        __syncthreads();
        #pragma unroll
        for (int ks = 0; ks < 8; ks++) {
            unsigned ah[2][4], al[2][4];
            #pragma unroll
            for (int mt = 0; mt < 2; mt++) {
                int base = (wm * 32 + mt * 16 + g) * SMW_A + ks * 8 + tg;
                ah[mt][0] = sAhi[base];           ah[mt][1] = sAhi[base + 8 * SMW_A];
                ah[mt][2] = sAhi[base + 4];       ah[mt][3] = sAhi[base + 8 * SMW_A + 4];
                al[mt][0] = sAlo[base];           al[mt][1] = sAlo[base + 8 * SMW_A];
                al[mt][2] = sAlo[base + 4];       al[mt][3] = sAlo[base + 8 * SMW_A + 4];
            }
            #pragma unroll
            for (int nt = 0; nt < 4; nt++) {
                int bb = (wn * 32 + nt * 8 + g) * SMW_A + ks * 8 + tg;
                unsigned bh0 = sWhi[bb], bh1 = sWhi[bb + 4];
                unsigned bl0 = sWlo[bb], bl1 = sWlo[bb + 4];
                #pragma unroll
                for (int mt = 0; mt < 2; mt++) {
                    mma16816(acc[mt][nt], ah[mt][0], ah[mt][1], ah[mt][2], ah[mt][3], bh0, bh1);
                    mma16816(acc[mt][nt], ah[mt][0], ah[mt][1], ah[mt][2], ah[mt][3], bl0, bl1);
                    mma16816(acc[mt][nt], al[mt][0], al[mt][1], al[mt][2], al[mt][3], bh0, bh1);
                }
            }
        }
    }
    #pragma unroll
    for (int mt = 0; mt < 2; mt++) {
        int r = wm * 32 + mt * 16 + g;
        #pragma unroll
        for (int nt = 0; nt < 4; nt++) {
            int cb = wn * 32 + nt * 8 + 2 * tg;
            float b0 = 0.f, b1 = 0.f;
            if (bias) { b0 = bias[cb]; b1 = bias[cb + 1]; }
            float2 v0 = {acc[mt][nt][0] + b0, acc[mt][nt][1] + b1};
            float2 v1 = {acc[mt][nt][2] + b0, acc[mt][nt][3] + b1};
            *(float2*)(C + r * ldc + cb) = v0;
            *(float2*)(C + (r + 8) * ldc + cb) = v1;
        }
    }
}

// ---------------- attention units ----------------
__device__ __noinline__ void scores_unit(int b, int sc, const float* __restrict__ ew, float* sm) {
    float* qs = sm;
    float* ws = sm + HH;
    int tid = threadIdx.x;
    __syncthreads();
    for (int i = tid; i < HH; i += NTHR) {
        float v = 0.f;
        #pragma unroll
        for (int p = 0; p < 8; p++) v += g_qpart[p][b * HH + i];
        qs[i] = v; ws[i] = ew[i];
    }
    __syncthreads();
    int warp = tid >> 5, lane = tid & 31;
    #pragma unroll
    for (int r = 0; r < 4; r++) {
        int s = sc * 32 + warp * 4 + r;
        const float* p = g_proj_key + (b * SS + s) * HH;
        float acc = 0.f;
        for (int h = lane * 4; h < HH; h += 128) {
            float4 pv = *(const float4*)(p + h);
            acc += fast_tanh(qs[h + 0] + pv.x) * ws[h + 0];
            acc += fast_tanh(qs[h + 1] + pv.y) * ws[h + 1];
            acc += fast_tanh(qs[h + 2] + pv.z) * ws[h + 2];
            acc += fast_tanh(qs[h + 3] + pv.w) * ws[h + 3];
        }
        #pragma unroll
        for (int o = 16; o; o >>= 1) acc += __shfl_xor_sync(0xffffffffu, acc, o);
        if (lane == 0) g_scores[b * SS + s] = acc;
    }
}

__device__ __noinline__ void ctx_unit(int b, int nc, const float* __restrict__ enc, float* sm) {
    float* ev = sm;
    float* red = sm + SS;
    int tid = threadIdx.x, warp = tid >> 5, lane = tid & 31;
    __syncthreads();
    float sv = (tid < SS) ? g_scores[b * SS + tid] : -3.0e38f;
    float m = sv;
    #pragma unroll
    for (int o = 16; o; o >>= 1) m = fmaxf(m, __shfl_xor_sync(0xffffffffu, m, o));
    if (lane == 0) red[warp] = m;
    __syncthreads();
    if (warp == 0) {
        float v = (lane < 8) ? red[lane] : -3.0e38f;
        #pragma unroll
        for (int o = 4; o; o >>= 1) v = fmaxf(v, __shfl_xor_sync(0xffffffffu, v, o));
        if (lane == 0) red[0] = v;
    }
    __syncthreads();
    float bmax = red[0];
    __syncthreads();
    float e = (tid < SS) ? __expf(sv - bmax) : 0.f;
    if (tid < SS) ev[tid] = e;
    float su = e;
    #pragma unroll
    for (int o = 16; o; o >>= 1) su += __shfl_xor_sync(0xffffffffu, su, o);
    if (lane == 0) red[warp] = su;
    __syncthreads();
    if (tid == 0) {
        float ts = 0.f;
        #pragma unroll
        for (int i = 0; i < 8; i++) ts += red[i];
        sm[136] = 1.0f / ts;
    }
    __syncthreads();
    float inv = sm[136];
    int n = nc * 256 + tid;
    const float* eb = enc + b * SS * 2 * HH + n;
    float acc = 0.f;
    #pragma unroll 8
    for (int s = 0; s < SS; s++) acc = fmaf(ev[s], eb[s * 2 * HH], acc);
    acc *= inv;
    int idx = b * 2 * HH + n;
    bf16 hi = __float2bfloat16(acc);
    g_chi[idx] = hi;
    g_clo[idx] = __float2bfloat16(acc - __bfloat162float(hi));
}

// ---------------- persistent decoder loop ----------------
__global__ void __launch_bounds__(NTHR) decoder_loop(
    const float* __restrict__ enc, const float* __restrict__ ew,
    const float* __restrict__ b_hh,
    float* __restrict__ out_states, float* __restrict__ out_hfinal,
    float* __restrict__ out_pre, int ncta) {
    extern __shared__ unsigned smext[];
    float* smf = (float*)smext;
    unsigned epoch = 0;
    const int bid = blockIdx.x;
    const int tid = threadIdx.x;
    const int ldw_ih = EE + 2 * HH;       // 2560
    const int ldw_pre = EE + 3 * HH;      // 3584

    for (int t = 0; t < TT; t++) {
        // ---- Pa: q [64u] + preout-h(prev state) [64u] ----
        for (int u = bid; u < 128; u += ncta) {
            if (u < 64) {
                int nt = u & 7, kc = u >> 3;
                mma_unit(g_hhi + kc * 128, g_hlo + kc * 128, HH,
                         g_qwhi + nt * 128 * HH + kc * 128, g_qwlo + nt * 128 * HH + kc * 128, HH,
                         g_qpart[kc] + nt * 128, HH, 1, nullptr, smext);
            } else {
                int v = u - 64; int nt = v & 7, kc = v >> 3;
                mma_unit(g_hhi + kc * 128, g_hlo + kc * 128, HH,
                         g_prehi + nt * 128 * ldw_pre + EE + kc * 128,
                         g_prelo + nt * 128 * ldw_pre + EE + kc * 128, ldw_pre,
                         g_phpart[kc] + nt * 128, HH, 1, nullptr, smext);
            }
        }
        gsync(epoch, ncta);
        // ---- Pb: scores [256u] + preout-final(t-1) [64u] ----
        {
            int nu = (t > 0) ? 320 : 256;
            for (int u = bid; u < nu; u += ncta) {
                if (u < 256) {
                    scores_unit(u >> 2, u & 3, ew, smf);
                } else {
                    int v = u - 256;
                    for (int e = tid; e < 1024; e += NTHR) {
                        int i = v * 1024 + e;
                        int b = i >> 10, k = i & 1023;
                        float val = g_pre_emb[(b * TT + (t - 1)) * HH + k];
                        #pragma unroll
                        for (int p = 0; p < 16; p++) val += g_pcpart[p][i];
                        #pragma unroll
                        for (int p = 0; p < 8; p++) val += g_phpart[p][i];
                        out_pre[(b * TT + (t - 1)) * HH + k] = val;
                    }
                }
            }
        }
        gsync(epoch, ncta);
        // ---- Pc: ctx [512u] + gh [192u] ----
        for (int u = bid; u < 704; u += ncta) {
            if (u < 512) {
                ctx_unit(u >> 3, u & 7, enc, smf);
            } else {
                int v = u - 512; int nt = v % 24, kc = v / 24;
                mma_unit(g_hhi + kc * 128, g_hlo + kc * 128, HH,
                         g_whhhi + nt * 128 * HH + kc * 128, g_whhlo + nt * 128 * HH + kc * 128, HH,
                         g_ghpart[kc] + nt * 128, 3 * HH, 1, nullptr, smext);
            }
        }
        gsync(epoch, ncta);
        // ---- Pd: gi [384u] + prectx [128u] ----
        for (int u = bid; u < 512; u += ncta) {
            if (u < 384) {
                int nt = u % 24, kc = u / 24;
                mma_unit(g_chi + kc * 128, g_clo + kc * 128, 2 * HH,
                         g_wihhi + nt * 128 * ldw_ih + EE + kc * 128,
                         g_wihlo + nt * 128 * ldw_ih + EE + kc * 128, ldw_ih,
                         g_gipart[kc] + nt * 128, 3 * HH, 1, nullptr, smext);
            } else {
                int v = u - 384; int nt = v & 7, kc = v >> 3;
                mma_unit(g_chi + kc * 128, g_clo + kc * 128, 2 * HH,
                         g_prehi + nt * 128 * ldw_pre + (EE + HH) + kc * 128,
                         g_prelo + nt * 128 * ldw_pre + (EE + HH) + kc * 128, ldw_pre,
                         g_pcpart[kc] + nt * 128, HH, 1, nullptr, smext);
            }
        }
        gsync(epoch, ncta);
        // ---- Pe: GRU combine + h split ----
        for (int idx = bid * NTHR + tid; idx < BB * HH; idx += ncta * NTHR) {
            int b = idx >> 10, k = idx & 1023;
            int r0 = b * 3 * HH + k;
            float ir = g_gi_emb[(b * TT + t) * 3 * HH + k];
            float iz = g_gi_emb[(b * TT + t) * 3 * HH + HH + k];
            float in_ = g_gi_emb[(b * TT + t) * 3 * HH + 2 * HH + k];
            #pragma unroll
            for (int p = 0; p < 16; p++) {
                ir  += g_gipart[p][r0];
                iz  += g_gipart[p][r0 + HH];
                in_ += g_gipart[p][r0 + 2 * HH];
            }
            float hr = b_hh[k], hz = b_hh[HH + k], hn = b_hh[2 * HH + k];
            #pragma unroll
            for (int p = 0; p < 8; p++) {
                hr += g_ghpart[p][r0];
                hz += g_ghpart[p][r0 + HH];
                hn += g_ghpart[p][r0 + 2 * HH];
            }
            float hp = g_h[idx];
            float r = sigmoidf_(ir + hr);
            float z = sigmoidf_(iz + hz);
            float n = fast_tanh(fmaf(r, hn, in_));
            float hnew = fmaf(z, hp - n, n);
            g_h[idx] = hnew;
            bf16 hi = __float2bfloat16(hnew);
            g_hhi[idx] = hi;
            g_hlo[idx] = __float2bfloat16(hnew - __bfloat162float(hi));
            out_states[(b * TT + t) * HH + k] = hnew;
            if (t == TT - 1) out_hfinal[idx] = hnew;
        }
        gsync(epoch, ncta);
    }
    // ---- tail: preout-h(127) + final sum ----
    for (int u = bid; u < 64; u += ncta) {
        int nt = u & 7, kc = u >> 3;
        mma_unit(g_hhi + kc * 128, g_hlo + kc * 128, HH,
                 g_prehi + nt * 128 * ldw_pre + EE + kc * 128,
                 g_prelo + nt * 128 * ldw_pre + EE + kc * 128, ldw_pre,
                 g_phpart[kc] + nt * 128, HH, 1, nullptr, smext);
    }
    gsync(epoch, ncta);
    for (int u = bid; u < 64; u += ncta) {
        for (int e = tid; e < 1024; e += NTHR) {
            int i = u * 1024 + e;
            int b = i >> 10, k = i & 1023;
            float val = g_pre_emb[(b * TT + TT - 1) * HH + k];
            #pragma unroll
            for (int p = 0; p < 16; p++) val += g_pcpart[p][i];
            #pragma unroll
            for (int p = 0; p < 8; p++) val += g_phpart[p][i];
            out_pre[(b * TT + TT - 1) * HH + k] = val;
        }
    }
}

// ---------------- precompute mma kernel ----------------
__global__ void __launch_bounds__(NTHR) mma_pre(const float* __restrict__ b_ih,
                                                float* __restrict__ dummy) {
    extern __shared__ unsigned smext[];
    int u = blockIdx.x;
    if (u < 1024) {                      // proj_key: 128m x 8n, K=2048
        int mt = u >> 3, nt = u & 7;
        mma_unit(g_ehi + mt * 64 * (2 * HH), g_elo + mt * 64 * (2 * HH), 2 * HH,
                 g_keyhi + nt * 128 * (2 * HH), g_keylo + nt * 128 * (2 * HH), 2 * HH,
                 g_proj_key + mt * 64 * HH + nt * 128, HH, 16, nullptr, smext);
    } else if (u < 1024 + 3072) {        // gi_emb: K=512, + b_ih
        int v = u - 1024; int mt = v / 24, nt = v % 24;
        mma_unit(g_thi + mt * 64 * EE, g_tlo + mt * 64 * EE, EE,
                 g_wihhi + nt * 128 * (EE + 2 * HH), g_wihlo + nt * 128 * (EE + 2 * HH),
                 EE + 2 * HH,
                 g_gi_emb + mt * 64 * 3 * HH + nt * 128, 3 * HH, 4, b_ih + nt * 128, smext);
    } else {                             // pre_emb: K=512
        int v = u - 4096; int mt = v >> 3, nt = v & 7;
        mma_unit(g_thi + mt * 64 * EE, g_tlo + mt * 64 * EE, EE,
                 g_prehi + nt * 128 * (EE + 3 * HH), g_prelo + nt * 128 * (EE + 3 * HH),
                 EE + 3 * HH,
                 g_pre_emb + mt * 64 * HH + nt * 128, HH, 4, nullptr, smext);
    }
}

// ---------------- merged split kernel (7 segments -> 1 launch) ----------------
struct SplitSeg { const float* src; bf16* hi; bf16* lo; };
struct SplitArgs { SplitSeg s[7]; int bounds[8]; };   // bounds in 4-elem chunks, cumulative

__global__ void __launch_bounds__(256) split_all(SplitArgs a) {
    int total = a.bounds[7];
    for (int c = blockIdx.x * 256 + threadIdx.x; c < total; c += gridDim.x * 256) {
        int si = 0;
        #pragma unroll
        for (int j = 1; j < 7; j++) si += (c >= a.bounds[j]);
        int off = (c - a.bounds[si]) * 4;
        float4 v = *(const float4*)(a.s[si].src + off);
        bf16 h0 = __float2bfloat16(v.x), h1 = __float2bfloat16(v.y);
        bf16 h2 = __float2bfloat16(v.z), h3 = __float2bfloat16(v.w);
        __nv_bfloat162* hp = (__nv_bfloat162*)(a.s[si].hi + off);
        hp[0] = __nv_bfloat162(h0, h1); hp[1] = __nv_bfloat162(h2, h3);
        __nv_bfloat162* lp = (__nv_bfloat162*)(a.s[si].lo + off);
        lp[0] = __nv_bfloat162(__float2bfloat16(v.x - __bfloat162float(h0)),
                               __float2bfloat16(v.y - __bfloat162float(h1)));
        lp[1] = __nv_bfloat162(__float2bfloat16(v.z - __bfloat162float(h2)),
                               __float2bfloat16(v.w - __bfloat162float(h3)));
    }
}

__global__ void split_kernel(const float* __restrict__ src, bf16* __restrict__ hi,
                             bf16* __restrict__ lo, int n) {
    for (int i = (blockIdx.x * 256 + threadIdx.x) * 4; i < n; i += gridDim.x * 256 * 4) {
        float4 v = *(const float4*)(src + i);
        bf16 h0 = __float2bfloat16(v.x), h1 = __float2bfloat16(v.y);
        bf16 h2 = __float2bfloat16(v.z), h3 = __float2bfloat16(v.w);
        __nv_bfloat162* hp = (__nv_bfloat162*)(hi + i);
        hp[0] = __nv_bfloat162(h0, h1); hp[1] = __nv_bfloat162(h2, h3);
        __nv_bfloat162* lp = (__nv_bfloat162*)(lo + i);
        lp[0] = __nv_bfloat162(__float2bfloat16(v.x - __bfloat162float(h0)),
                               __float2bfloat16(v.y - __bfloat162float(h1)));
        lp[1] = __nv_bfloat162(__float2bfloat16(v.z - __bfloat162float(h2)),
                               __float2bfloat16(v.w - __bfloat162float(h3)));
    }
}

// ---------------- h0 SIMT GEMM: h0 = tanh(enc_final @ bridgeW^T + b) ----------------
__global__ void __launch_bounds__(256) gemm_h0(const float* __restrict__ A,
                                               const float* __restrict__ W,
                                               const float* __restrict__ bias,
                                               float* __restrict__ C) {
    int ntile = blockIdx.x;
    const float* Wbase = W + ntile * 32 * (2 * HH);
    __shared__ float As[32][68];
    __shared__ float Ws[32][34];
    int tid = threadIdx.x;
    int nhat = tid & 15, mhat = tid >> 4;
    int lr = tid >> 3, lc = (tid & 7) << 2;
    float acc[4][2] = {};
    for (int k0 = 0; k0 < 2 * HH; k0 += 32) {
        float4 a0 = *(const float4*)(A + lr * (2 * HH) + k0 + lc);
        float4 a1 = *(const float4*)(A + (lr + 32) * (2 * HH) + k0 + lc);
        float4 w0 = *(const float4*)(Wbase + lr * (2 * HH) + k0 + lc);
        __syncthreads();
        As[lc + 0][lr] = a0.x; As[lc + 1][lr] = a0.y; As[lc + 2][lr] = a0.z; As[lc + 3][lr] = a0.w;
        As[lc + 0][lr + 32] = a1.x; As[lc + 1][lr + 32] = a1.y;
        As[lc + 2][lr + 32] = a1.z; As[lc + 3][lr + 32] = a1.w;
        Ws[lc + 0][lr] = w0.x; Ws[lc + 1][lr] = w0.y; Ws[lc + 2][lr] = w0.z; Ws[lc + 3][lr] = w0.w;
        __syncthreads();
        #pragma unroll
        for (int kk = 0; kk < 32; kk++) {
            float4 av = *(const float4*)&As[kk][mhat << 2];
            float2 wv = *(const float2*)&Ws[kk][nhat << 1];
            acc[0][0] = fmaf(av.x, wv.x, acc[0][0]); acc[0][1] = fmaf(av.x, wv.y, acc[0][1]);
            acc[1][0] = fmaf(av.y, wv.x, acc[1][0]); acc[1][1] = fmaf(av.y, wv.y, acc[1][1]);
            acc[2][0] = fmaf(av.z, wv.x, acc[2][0]); acc[2][1] = fmaf(av.z, wv.y, acc[2][1]);
            acc[3][0] = fmaf(av.w, wv.x, acc[3][0]); acc[3][1] = fmaf(av.w, wv.y, acc[3][1]);
        }
    }
    int nbase = ntile * 32 + (nhat << 1);
    #pragma unroll
    for (int i = 0; i < 4; i++)
        #pragma unroll
        for (int j = 0; j < 2; j++) {
            int m = (mhat << 2) + i, n = nbase + j;
            C[m * HH + n] = fast_tanh(acc[i][j] + bias[n]);
        }
}

__global__ void zero_ctr() { g_ctr = 0u; }

// ---------------- host ----------------
extern "C" void kernel_launch(void* const* d_in, const int* in_sizes, int n_in,
                              void* d_out, int out_size) {
    const float* trg_embed  = (const float*)d_in[0];
    const float* enc_hidden = (const float*)d_in[1];
    const float* enc_final  = (const float*)d_in[2];
    const float* key_W    = (const float*)d_in[4];
    const float* query_W  = (const float*)d_in[5];
    const float* energy_w = (const float*)d_in[6];
    const float* W_ih     = (const float*)d_in[7];
    const float* W_hh     = (const float*)d_in[8];
    const float* b_ih     = (const float*)d_in[9];
    const float* b_hh     = (const float*)d_in[10];
    const float* bridge_W = (const float*)d_in[11];
    const float* bridge_b = (const float*)d_in[12];
    const float* preout_W = (const float*)d_in[13];

    cudaFuncSetAttribute(decoder_loop, cudaFuncAttributeMaxDynamicSharedMemorySize,
                         SM_WORDS * 4);
    cudaFuncSetAttribute(mma_pre, cudaFuncAttributeMaxDynamicSharedMemorySize,
                         SM_WORDS * 4);

    // Occupancy-safe persistent grid: 1 or 2 CTAs/SM depending on smem fit.
    int occ = 1;
    cudaOccupancyMaxActiveBlocksPerMultiprocessor(&occ, decoder_loop, NTHR, SM_WORDS * 4);
    if (occ < 1) occ = 1;
    if (occ > 2) occ = 2;
    int ncta = 148 * occ;

    bf16 *ehi, *elo, *thi, *tlo, *khi, *klo, *qhi, *qlo, *whi, *wlo, *ihi, *ilo, *phi, *plo,
         *hhi, *hlo;
    float* p_h;
    cudaGetSymbolAddress((void**)&ehi, g_ehi);  cudaGetSymbolAddress((void**)&elo, g_elo);
    cudaGetSymbolAddress((void**)&thi, g_thi);  cudaGetSymbolAddress((void**)&tlo, g_tlo);
    cudaGetSymbolAddress((void**)&khi, g_keyhi); cudaGetSymbolAddress((void**)&klo, g_keylo);
    cudaGetSymbolAddress((void**)&qhi, g_qwhi); cudaGetSymbolAddress((void**)&qlo, g_qwlo);
    cudaGetSymbolAddress((void**)&whi, g_whhhi); cudaGetSymbolAddress((void**)&wlo, g_whhlo);
    cudaGetSymbolAddress((void**)&ihi, g_wihhi); cudaGetSymbolAddress((void**)&ilo, g_wihlo);
    cudaGetSymbolAddress((void**)&phi, g_prehi); cudaGetSymbolAddress((void**)&plo, g_prelo);
    cudaGetSymbolAddress((void**)&hhi, g_hhi);  cudaGetSymbolAddress((void**)&hlo, g_hlo);
    cudaGetSymbolAddress((void**)&p_h, g_h);

    float* out_states = (float*)d_out;
    float* out_hfinal = out_states + BB * TT * HH;
    float* out_pre    = out_hfinal + BB * HH;

    // launch 0: merged split of all 7 fp32 tensors -> bf16 hi/lo
    {
        SplitArgs sa;
        const float* srcs[7] = {enc_hidden, trg_embed, key_W, query_W, W_hh, W_ih, preout_W};
        bf16* his[7] = {ehi, thi, khi, qhi, whi, ihi, phi};
        bf16* los[7] = {elo, tlo, klo, qlo, wlo, ilo, plo};
        int ns[7] = {BB * SS * 2 * HH, BB * TT * EE, HH * 2 * HH, HH * HH,
                     3 * HH * HH, 3 * HH * (EE + 2 * HH), HH * (3 * HH + EE)};
        sa.bounds[0] = 0;
        for (int j = 0; j < 7; j++) {
            sa.s[j].src = srcs[j]; sa.s[j].hi = his[j]; sa.s[j].lo = los[j];
            sa.bounds[j + 1] = sa.bounds[j] + ns[j] / 4;
        }
        split_all<<<2048, 256>>>(sa);
    }
    // launch 1: h0 = tanh(bridge(enc_final))
    gemm_h0<<<32, 256>>>(enc_final, bridge_W, bridge_b, p_h);
    // launch 2: split h0
    split_kernel<<<64, 256>>>(p_h, hhi, hlo, BB * HH);
    // launch 3: precompute GEMMs (HMMA)
    mma_pre<<<5120, 256, SM_WORDS * 4>>>(b_ih, nullptr);
    // launch 4: reset grid-barrier counter
    zero_ctr<<<1, 1>>>();
    // launch 5: persistent decode loop — ncu -s 5 -c 1 lands here
    decoder_loop<<<ncta, NTHR, SM_WORDS * 4>>>(enc_hidden, energy_w, b_hh,
                                               out_states, out_hfinal, out_pre, ncta);
}